// round 3
// baseline (speedup 1.0000x reference)
#include <cuda_runtime.h>
#include <cuda_bf16.h>
#include <math.h>

// Problem constants
#define BATCH   4
#define SEQ     4096
#define CMODEL  2048
#define NHEAD   16
#define HDIM    128
#define NLAT    64
#define HL      (NHEAD * NLAT)     // 1024
#define SCALE_F (0.08838834764831845f) // 1/sqrt(128)

// ---------------- device scratch (no allocations allowed) ----------------
__device__ float g_k[BATCH * NLAT * CMODEL];            // k rows t<64:  [B,64,H,D] = 2MB
__device__ float g_v[BATCH * NLAT * CMODEL];            // v rows t<64
__device__ float g_attn[BATCH * NHEAD * NLAT * HDIM];   // [B,H,64,128] = 2MB
__device__ float g_P[(long long)BATCH * HL * CMODEL];   // [B, 1024, 2048] = 32MB
__device__ float g_gates[(long long)BATCH * SEQ * HL];  // [B*T, 1024] = 64MB

// ---------------- generic batched SGEMM (row-major, fp32) ----------------
// C[M,N] = A[M,K] @ B[K,N], lda=K, ldb=N, ldc=N.
// z-batch: Aoff = z*aStride, Boff = (bModulo? z%bModulo : z)*bStride, Coff = z*cStride
#define BM 128
#define BN 128
#define BKK 8
#define TM 8
#define TN 8

__global__ __launch_bounds__(256) void sgemm_batched(
    const float* __restrict__ A, const float* __restrict__ B, float* __restrict__ C,
    int M, int N, int K,
    long long aStride, long long bStride, long long cStride, int bModulo)
{
    int z = blockIdx.z;
    A += (long long)z * aStride;
    B += (long long)(bModulo > 0 ? (z % bModulo) : z) * bStride;
    C += (long long)z * cStride;

    __shared__ float As[BKK][BM];
    __shared__ float Bs[BKK][BN];

    const int tid = threadIdx.x;          // 256 threads
    const int blockRow = blockIdx.y * BM;
    const int blockCol = blockIdx.x * BN;
    const int tx = tid % (BN / TN);       // 0..15
    const int ty = tid / (BN / TN);       // 0..15

    float acc[TM][TN];
    #pragma unroll
    for (int i = 0; i < TM; i++)
        #pragma unroll
        for (int j = 0; j < TN; j++) acc[i][j] = 0.f;

    const int aRow  = tid / (BKK / 4);        // 0..127
    const int aCol4 = (tid % (BKK / 4)) * 4;  // 0 or 4
    const int bRow  = tid / (BN / 4);         // 0..7
    const int bCol4 = (tid % (BN / 4)) * 4;   // 0..124

    for (int k0 = 0; k0 < K; k0 += BKK) {
        // Load A tile (transposed into smem). Guard M (M may be 64).
        float4 av = make_float4(0.f, 0.f, 0.f, 0.f);
        int gRow = blockRow + aRow;
        if (gRow < M)
            av = *reinterpret_cast<const float4*>(&A[(long long)gRow * K + k0 + aCol4]);
        As[aCol4 + 0][aRow] = av.x;
        As[aCol4 + 1][aRow] = av.y;
        As[aCol4 + 2][aRow] = av.z;
        As[aCol4 + 3][aRow] = av.w;
        // Load B tile. N is always a multiple of 128, K multiple of 8.
        float4 bv = *reinterpret_cast<const float4*>(&B[(long long)(k0 + bRow) * N + blockCol + bCol4]);
        *reinterpret_cast<float4*>(&Bs[bRow][bCol4]) = bv;
        __syncthreads();

        #pragma unroll
        for (int kk = 0; kk < BKK; kk++) {
            float ra[TM], rb[TN];
            #pragma unroll
            for (int i = 0; i < TM; i++) ra[i] = As[kk][ty * TM + i];
            #pragma unroll
            for (int j = 0; j < TN; j++) rb[j] = Bs[kk][tx * TN + j];
            #pragma unroll
            for (int i = 0; i < TM; i++)
                #pragma unroll
                for (int j = 0; j < TN; j++)
                    acc[i][j] += ra[i] * rb[j];
        }
        __syncthreads();
    }

    #pragma unroll
    for (int i = 0; i < TM; i++) {
        int gRow = blockRow + ty * TM + i;
        if (gRow >= M) continue;
        #pragma unroll
        for (int j = 0; j < TN; j += 4) {
            float4 v = make_float4(acc[i][j], acc[i][j + 1], acc[i][j + 2], acc[i][j + 3]);
            *reinterpret_cast<float4*>(&C[(long long)gRow * N + blockCol + tx * TN + j]) = v;
        }
    }
}

// ---------------- RoPE on g_k : [B, 64, H, D], pairs (2i, 2i+1) ----------------
__global__ void rope_kernel(float* __restrict__ k)
{
    int idx = blockIdx.x * blockDim.x + threadIdx.x; // B*64*H*64 = 262144
    if (idx >= BATCH * NLAT * NHEAD * (HDIM / 2)) return;
    int i = idx & 63;
    int h = (idx >> 6) & 15;
    int t = (idx >> 10) & 63;
    int b = idx >> 16;
    // inv_freq = 10000^(-2i/128) = exp(-(2i/128)*ln(10000))
    float inv_freq = expf(-(2.0f * i / 128.0f) * 9.210340371976184f);
    float ang = (float)t * inv_freq;
    float c, s;
    __sincosf(ang, &s, &c);
    long long base = ((((long long)b * NLAT + t) * NHEAD + h) * HDIM) + 2 * i;
    float x0 = k[base], x1 = k[base + 1];
    k[base]     = x0 * c - x1 * s;
    k[base + 1] = x0 * s + x1 * c;
}

// ---------------- tiny causal attention over the first 64 positions ----------------
// one block per (b,h); attn[b,h,l,d] = sum_{t<=l} softmax(q_l . k_t * SCALE) * v[t,d]
__global__ __launch_bounds__(256) void attn_kernel(
    const float* __restrict__ lq,   // [64, 16, 128]  (latent_queries)
    const float* __restrict__ k,    // [B, 64, 16, 128]
    const float* __restrict__ v,    // [B, 64, 16, 128]
    float* __restrict__ attn)       // [B, 16, 64, 128]
{
    const int b = blockIdx.x >> 4;
    const int h = blockIdx.x & 15;
    const int tid = threadIdx.x;

    __shared__ float sS[NLAT * NLAT];     // 16KB scores/weights
    __shared__ float sV[NLAT * HDIM];     // 32KB V tile

    for (int i = tid; i < NLAT * HDIM; i += 256) {
        int t = i >> 7, d = i & 127;
        sV[i] = v[((((long long)b * NLAT + t) * NHEAD + h) * HDIM) + d];
    }

    // scores
    for (int i = tid; i < NLAT * NLAT; i += 256) {
        int l = i >> 6, t = i & 63;
        float s = -1e9f;
        if (t <= l) {
            const float* qp = lq + ((long long)l * NHEAD + h) * HDIM;
            const float* kp = k + (((long long)b * NLAT + t) * NHEAD + h) * HDIM;
            float acc = 0.f;
            #pragma unroll 4
            for (int d = 0; d < HDIM; d++) acc += qp[d] * kp[d];
            s = acc * SCALE_F;
        }
        sS[i] = s;
    }
    __syncthreads();

    // per-row softmax (rows = latents)
    if (tid < NLAT) {
        int l = tid;
        float m = -1e30f;
        for (int t = 0; t < NLAT; t++) m = fmaxf(m, sS[l * NLAT + t]);
        float sum = 0.f;
        for (int t = 0; t < NLAT; t++) {
            float e = __expf(sS[l * NLAT + t] - m);
            sS[l * NLAT + t] = e;
            sum += e;
        }
        float inv = 1.0f / sum;
        for (int t = 0; t < NLAT; t++) sS[l * NLAT + t] *= inv;
    }
    __syncthreads();

    // attn = W @ V
    for (int i = tid; i < NLAT * HDIM; i += 256) {
        int l = i >> 7, d = i & 127;
        float acc = 0.f;
        #pragma unroll 4
        for (int t = 0; t < NLAT; t++) acc += sS[l * NLAT + t] * sV[t * HDIM + d];
        attn[((((long long)b * NHEAD + h) * NLAT + l) * HDIM) + d] = acc;
    }
}

// ---------------- gate softmax: groups of 64 along last dim, times SCALE ----------------
__global__ void gate_softmax(float* __restrict__ g)
{
    // one warp per group of 64; total groups = B*T*H = 262144
    int gw = (blockIdx.x * blockDim.x + threadIdx.x) >> 5;
    int lane = threadIdx.x & 31;
    if (gw >= BATCH * SEQ * NHEAD) return;
    long long base = (long long)gw * 64;
    float v0 = g[base + lane] * SCALE_F;
    float v1 = g[base + 32 + lane] * SCALE_F;
    float m = fmaxf(v0, v1);
    #pragma unroll
    for (int o = 16; o; o >>= 1) m = fmaxf(m, __shfl_xor_sync(0xffffffffu, m, o));
    float e0 = __expf(v0 - m), e1 = __expf(v1 - m);
    float s = e0 + e1;
    #pragma unroll
    for (int o = 16; o; o >>= 1) s += __shfl_xor_sync(0xffffffffu, s, o);
    float inv = 1.0f / s;
    g[base + lane] = e0 * inv;
    g[base + 32 + lane] = e1 * inv;
}

// ---------------- launch ----------------
extern "C" void kernel_launch(void* const* d_in, const int* in_sizes, int n_in,
                              void* d_out, int out_size)
{
    const float* x  = (const float*)d_in[0];  // [4,4096,2048]
    const float* lq = (const float*)d_in[1];  // [1,64,16,128]
    const float* Wk = (const float*)d_in[2];  // [2048,2048]
    const float* Wv = (const float*)d_in[3];
    const float* Wg = (const float*)d_in[4];  // [2048,1024]
    const float* Wp = (const float*)d_in[5];  // [2048,2048]
    float* out = (float*)d_out;               // [4,4096,2048]

    float *kbuf, *vbuf, *attnbuf, *Pbuf, *gatesbuf;
    cudaGetSymbolAddress((void**)&kbuf, g_k);
    cudaGetSymbolAddress((void**)&vbuf, g_v);
    cudaGetSymbolAddress((void**)&attnbuf, g_attn);
    cudaGetSymbolAddress((void**)&Pbuf, g_P);
    cudaGetSymbolAddress((void**)&gatesbuf, g_gates);

    // 1) k = x[:, :64] @ Wk ; v = x[:, :64] @ Wv   (batched over B)
    {
        dim3 grid(CMODEL / BN, (NLAT + BM - 1) / BM, BATCH);
        sgemm_batched<<<grid, 256>>>(x, Wk, kbuf, NLAT, CMODEL, CMODEL,
                                     (long long)SEQ * CMODEL, 0LL,
                                     (long long)NLAT * CMODEL, 1);
        sgemm_batched<<<grid, 256>>>(x, Wv, vbuf, NLAT, CMODEL, CMODEL,
                                     (long long)SEQ * CMODEL, 0LL,
                                     (long long)NLAT * CMODEL, 1);
    }

    // 2) RoPE on k (positions 0..63)
    rope_kernel<<<(BATCH * NLAT * NHEAD * (HDIM / 2) + 255) / 256, 256>>>(kbuf);

    // 3) attention -> attn [B,H,64,128]
    attn_kernel<<<BATCH * NHEAD, 256>>>(lq, kbuf, vbuf, attnbuf);

    // 4) P[b,h,l,:] = attn[b,h,l,:] @ Wp[h*128:(h+1)*128, :]   (batched over b*h)
    {
        dim3 grid(CMODEL / BN, 1, BATCH * NHEAD);
        sgemm_batched<<<grid, 256>>>(attnbuf, Wp, Pbuf, NLAT, CMODEL, HDIM,
                                     (long long)NLAT * HDIM,
                                     (long long)HDIM * CMODEL,
                                     (long long)NLAT * CMODEL, NHEAD);
    }

    // 5) gates = x @ Wg  ([16384,2048]@[2048,1024]) then softmax(SCALE*.) per 64-group
    {
        dim3 grid(HL / BN, (BATCH * SEQ) / BM, 1);
        sgemm_batched<<<grid, 256>>>(x, Wg, gatesbuf, BATCH * SEQ, HL, CMODEL,
                                     0LL, 0LL, 0LL, 1);
    }
    gate_softmax<<<(BATCH * SEQ * NHEAD * 32 + 255) / 256, 256>>>(gatesbuf);

    // 6) out[b] = gates[b] [4096,1024] @ P[b] [1024,2048]
    {
        dim3 grid(CMODEL / BN, SEQ / BM, BATCH);
        sgemm_batched<<<grid, 256>>>(gatesbuf, Pbuf, out, SEQ, CMODEL, HL,
                                     (long long)SEQ * HL,
                                     (long long)HL * CMODEL,
                                     (long long)SEQ * CMODEL, 0);
    }
}